// round 11
// baseline (speedup 1.0000x reference)
#include <cuda_runtime.h>

// Time2Vec: out[b,l,d*64+e] = (e==0) ? x*W[d,0]+b[d,0] : sin(x*W[d,e]+b[d,e])
// x: (32,4096,8) fp32, W/b: (8,64) fp32, out: (32,4096,512) fp32 = 16,777,216 quads.
//
// Converged write-stream kernel (~5.1-5.2 TB/s effective). Proven choices:
// 16KB dense tiles (R8/R9 parabola), st.global.wt (R10 best), direct STG.128,
// loop-invariant (d,e)/w4/b4. This round: THREADS=128 + ITER=8 at the SAME
// 16KB tile / 16384 blocks — finer CTA replacement granularity (16 slots/SM)
// and deeper per-thread store ILP. Per-iter stride = 128 quads = exactly the
// (d,e)-invariance boundary.

constexpr int N_QUADS     = 1 << 24;                 // 16,777,216
constexpr int THREADS     = 128;
constexpr int ITER        = 8;
constexpr int BLOCK_QUADS = THREADS * ITER;          // 1024 quads = 16 KB contiguous
constexpr int BLOCKS      = N_QUADS / BLOCK_QUADS;   // 16384
constexpr int XITER       = THREADS / 16;            // 8 x-elements per iter step

__global__ __launch_bounds__(THREADS, 16)
void time2vec_kernel(const float* __restrict__ x,
                     const float* __restrict__ W,
                     const float* __restrict__ B,
                     float4* __restrict__ out)
{
    const int tid = threadIdx.x;
    const int q0 = blockIdx.x * BLOCK_QUADS + tid;

    // loop-invariant coordinates: block offset mult of 1024, per-iter stride
    // 128 quads -> (d,e) depend only on tid.
    const int e = (tid & 15) << 2;       // starting e within [0,64)
    const int d = (tid >> 4) & 7;        // D = 8 (tid>>4 in [0,8))
    const bool first = (e == 0);         // passthrough lane

    const float4 w4 = __ldg((const float4*)(W + d * 64 + e));
    const float4 b4 = __ldg((const float4*)(B + d * 64 + e));

    const int x0 = q0 >> 4;

    // front-batch the streaming x loads (each read exactly once, MLP=8)
    float xv[ITER];
    #pragma unroll
    for (int i = 0; i < ITER; i++)
        xv[i] = __ldcs(&x[x0 + i * XITER]);

    #pragma unroll
    for (int i = 0; i < ITER; i++) {
        const float v0 = fmaf(xv[i], w4.x, b4.x);
        float4 r;
        r.x = first ? v0 : __sinf(v0);
        r.y = __sinf(fmaf(xv[i], w4.y, b4.y));
        r.z = __sinf(fmaf(xv[i], w4.z, b4.z));
        r.w = __sinf(fmaf(xv[i], w4.w, b4.w));

        __stwt(&out[q0 + i * THREADS], r);   // dense 16KB per block
    }
}

extern "C" void kernel_launch(void* const* d_in, const int* in_sizes, int n_in,
                              void* d_out, int out_size)
{
    const float* x = (const float*)d_in[0];
    const float* W = (const float*)d_in[1];
    const float* B = (const float*)d_in[2];
    time2vec_kernel<<<BLOCKS, THREADS>>>(x, W, B, (float4*)d_out);
}

// round 12
// speedup vs baseline: 1.0624x; 1.0624x over previous
#include <cuda_runtime.h>

// Time2Vec: out[b,l,d*64+e] = (e==0) ? x*W[d,0]+b[d,0] : sin(x*W[d,e]+b[d,e])
// x: (32,4096,8) fp32, W/b: (8,64) fp32, out: (32,4096,512) fp32 = 16,777,216 quads.
//
// FINAL converged kernel (session champion, 43.5us = ~5.1 TB/s effective
// write stream — at the HBM write-turnaround/LTS floor; DRAM-spec roofline
// is unreachable for pure writes). Proven-optimal choices, each bench-tested:
//   - 256 threads x ITER=4 -> 16KB dense tile per block, 16384 blocks
//     (tile/block geometry is a measured parabola with this at the minimum)
//   - direct STG.128 with st.global.wt (beats .cs slightly; TMA and v8 lose)
//   - loop-invariant (d,e): every addressing stride is a multiple of 128
//     quads, so w4/b4 are per-thread registers; zero shared memory
//   - front-batched __ldcs x loads (each x element read exactly once)
//   - __sinf (MUFU): abs err ~1e-5, rel_err 1.8e-07 vs reference

constexpr int N_QUADS     = 1 << 24;                 // 16,777,216
constexpr int THREADS     = 256;
constexpr int ITER        = 4;
constexpr int BLOCK_QUADS = THREADS * ITER;          // 1024 quads = 16 KB contiguous
constexpr int BLOCKS      = N_QUADS / BLOCK_QUADS;   // 16384
constexpr int XITER       = THREADS / 16;            // 16 x-elements per iter step

__global__ __launch_bounds__(THREADS, 8)
void time2vec_kernel(const float* __restrict__ x,
                     const float* __restrict__ W,
                     const float* __restrict__ B,
                     float4* __restrict__ out)
{
    const int q0 = blockIdx.x * BLOCK_QUADS + threadIdx.x;

    // loop-invariant coordinates (block offset mult of 1024, per-iter stride
    // 256 — both multiples of 128 quads -> (d,e) depend only on tid)
    const int e = (q0 & 15) << 2;        // starting e within [0,64)
    const int d = (q0 >> 4) & 7;         // D = 8
    const bool first = (e == 0);         // passthrough lane

    const float4 w4 = __ldg((const float4*)(W + d * 64 + e));
    const float4 b4 = __ldg((const float4*)(B + d * 64 + e));

    const int x0 = q0 >> 4;

    // front-batch the streaming x loads (each read exactly once)
    float xv[ITER];
    #pragma unroll
    for (int i = 0; i < ITER; i++)
        xv[i] = __ldcs(&x[x0 + i * XITER]);

    #pragma unroll
    for (int i = 0; i < ITER; i++) {
        const float v0 = fmaf(xv[i], w4.x, b4.x);
        float4 r;
        r.x = first ? v0 : __sinf(v0);
        r.y = __sinf(fmaf(xv[i], w4.y, b4.y));
        r.z = __sinf(fmaf(xv[i], w4.z, b4.z));
        r.w = __sinf(fmaf(xv[i], w4.w, b4.w));

        __stwt(&out[q0 + i * THREADS], r);   // dense 16KB per block
    }
}

extern "C" void kernel_launch(void* const* d_in, const int* in_sizes, int n_in,
                              void* d_out, int out_size)
{
    const float* x = (const float*)d_in[0];
    const float* W = (const float*)d_in[1];
    const float* B = (const float*)d_in[2];
    time2vec_kernel<<<BLOCKS, THREADS>>>(x, W, B, (float4*)d_out);
}